// round 12
// baseline (speedup 1.0000x reference)
#include <cuda_runtime.h>

// out: [16384, 2046] f32 = tanh(row) broadcast over batch rows; row depends
// only on kernel_weights[6]. `values` is shape-only.
//
// Converged model (R4..R11): replay period is pinned at ~25.2us = 134MB at
// ~5.3TB/s sustained DRAM write; kernel-internal changes conserve total.
// R12: remove the last physical inefficiency — partial-sector stores.
// 2-row period (16368B) is 16 mod 32, so half the store spans straddle 32B
// sectors / 128B lines. 16-row period = 130,944B = 0 mod 128: every warp
// writes a fully aligned, fully covered 512B span; zero partial sectors.
//
// 16 rows = 32736 floats = 8184 float4 slots. Grid (32, 64) = 2048 CTAs x
// 256 thr; 32 blocks x 256 = 8192 threads cover 8184 slots; 64 y-chunks x
// 16 groups = 1024 sixteen-row groups. Same approx prologue + __stwt.

#define BS        16384
#define L_OUT     2046
#define F4_PER_G  8184                 // float4 per 16-row group
#define GROUPS    (BS / 16)            // 1024
#define TPB       256
#define COL_BLK   32                   // 32*256 = 8192 threads cover 8184 slots
#define G_CHUNKS  64                   // batch split over blockIdx.y
#define G_PER_B   (GROUPS / G_CHUNKS)  // 16 stores per thread

#define NEG_LOG_NORM 1.3836465597893728f   // -log(0.1*sqrt(2*pi))
#define INV_STD      10.0f

__device__ __forceinline__ float tanh_approx(float x) {
    float y;
    asm("tanh.approx.f32 %0, %1;" : "=f"(y) : "f"(x));
    return y;
}

__device__ __forceinline__ float row_value(int c, const float* __restrict__ w) {
    const float means[6] = {0.0f, 0.2f, 0.4f, 0.6f, 0.8f, 1.0f};
    float pos = (float)c / (float)L_OUT;
    float acc = 0.0f;
#pragma unroll
    for (int k = 0; k < 6; k++) {
        float z = (pos - means[k]) * INV_STD;
        float pdf = __expf(fmaf(-0.5f * z, z, NEG_LOG_NORM));  // ex2.approx
        acc = fmaf(w[k], pdf, acc);
    }
    return tanh_approx(acc);
}

__global__ void __launch_bounds__(TPB) bcast_aln_kernel(const float* __restrict__ kw,
                                                        float4* __restrict__ out) {
    int t = blockIdx.x * TPB + threadIdx.x;    // float4 slot within a 16-row group
    if (t >= F4_PER_G) return;                  // 8 of 8192 threads idle

    float w[6];
#pragma unroll
    for (int k = 0; k < 6; k++) w[k] = 0.25f * tanh_approx(__ldg(&kw[k]));

    // Columns for this slot: (4t + i) mod 2046, i in 0..3  (4t < 32736)
    int e = 4 * t;
    int c0 = e % L_OUT;
    int c1 = c0 + 1; if (c1 >= L_OUT) c1 -= L_OUT;
    int c2 = c1 + 1; if (c2 >= L_OUT) c2 -= L_OUT;
    int c3 = c2 + 1; if (c3 >= L_OUT) c3 -= L_OUT;

    float4 v;
    v.x = row_value(c0, w);
    v.y = row_value(c1, w);
    v.z = row_value(c2, w);
    v.w = row_value(c3, w);

    // 128B-aligned warp spans; group stride 130,944B (0 mod 128).
    float4* p = out + (size_t)blockIdx.y * G_PER_B * F4_PER_G + t;
#pragma unroll 8
    for (int g = 0; g < G_PER_B; g++) {
        __stwt(p, v);          // write-through STG.128
        p += F4_PER_G;
    }
}

extern "C" void kernel_launch(void* const* d_in, const int* in_sizes, int n_in,
                              void* d_out, int out_size) {
    const float* kw = (const float*)d_in[1];   // kernel_weights [6]
    dim3 grid(COL_BLK, G_CHUNKS);              // 2048 CTAs x 256 threads
    bcast_aln_kernel<<<grid, TPB>>>(kw, (float4*)d_out);
}

// round 13
// speedup vs baseline: 1.0102x; 1.0102x over previous
#include <cuda_runtime.h>

// out: [16384, 2046] f32 = tanh(row) broadcast over batch rows; row depends
// only on kernel_weights[6]. `values` is shape-only.
//
// FINAL (R4 record config, 25.12us). Converged analysis (R4..R12): the
// replay period is pinned at ~25.2us = 134MB output at ~5.3TB/s sustained
// DRAM write — the hardware floor for this problem's mandatory bytes.
// Store width, cache policy, L2-residency splits, wave shape, tiling period
// and prologue cost all conserve this total (8 variants within 0.2us).
//
// Structure: pattern period = 2 rows = 4092 floats = 1023 float4 (16B
// aligned). Each thread owns one float4 column slot, computes its 4 values
// once into registers, then streams write-through STG.128 down the batch
// dimension (wt: single LTS pass, no write-allocate/writeback double pass).
// libm tanhf/expf kept for the best accuracy margin (rel_err 2.1e-7).

#define BS       16384
#define L_OUT    2046
#define GROUPS   (BS / 2)              // 8192 two-row groups
#define F4_PER_G 1023                  // float4 per group
#define TPB      256
#define COL_BLK  4                     // 4*256 = 1024 threads cover 1023 slots
#define G_CHUNKS 512                   // batch split over blockIdx.y
#define G_PER_B  (GROUPS / G_CHUNKS)   // 16 stores per thread

#define NEG_LOG_NORM 1.3836465597893728f   // -log(0.1*sqrt(2*pi))
#define INV_STD      10.0f

__device__ __forceinline__ float row_value(int c, const float* __restrict__ w) {
    const float means[6] = {0.0f, 0.2f, 0.4f, 0.6f, 0.8f, 1.0f};
    float pos = (float)c / (float)L_OUT;
    float acc = 0.0f;
#pragma unroll
    for (int k = 0; k < 6; k++) {
        float z = (pos - means[k]) * INV_STD;
        float pdf = expf(fmaf(-0.5f * z, z, NEG_LOG_NORM));
        acc = fmaf(w[k], pdf, acc);
    }
    return tanhf(acc);
}

__global__ void __launch_bounds__(TPB) bcast_wt_kernel(const float* __restrict__ kw,
                                                       float4* __restrict__ out) {
    int t = blockIdx.x * TPB + threadIdx.x;    // float4 slot within a group
    if (t >= F4_PER_G) return;

    float w[6];
#pragma unroll
    for (int k = 0; k < 6; k++) w[k] = 0.25f * tanhf(__ldg(&kw[k]));

    int e = 4 * t;
    int c0 = e;     if (c0 >= L_OUT) c0 -= L_OUT;
    int c1 = e + 1; if (c1 >= L_OUT) c1 -= L_OUT;
    int c2 = e + 2; if (c2 >= L_OUT) c2 -= L_OUT;
    int c3 = e + 3; if (c3 >= L_OUT) c3 -= L_OUT;

    float4 v;
    v.x = row_value(c0, w);
    v.y = row_value(c1, w);
    v.z = row_value(c2, w);
    v.w = row_value(c3, w);

    float4* p = out + (size_t)blockIdx.y * G_PER_B * F4_PER_G + t;
#pragma unroll 8
    for (int g = 0; g < G_PER_B; g++) {
        __stwt(p, v);          // write-through: one LTS pass, no writeback
        p += F4_PER_G;
    }
}

extern "C" void kernel_launch(void* const* d_in, const int* in_sizes, int n_in,
                              void* d_out, int out_size) {
    const float* kw = (const float*)d_in[1];   // kernel_weights [6]
    dim3 grid(COL_BLK, G_CHUNKS);              // 2048 blocks x 256 threads
    bcast_wt_kernel<<<grid, TPB>>>(kw, (float4*)d_out);
}